// round 5
// baseline (speedup 1.0000x reference)
#include <cuda_runtime.h>
#include <cuda_fp16.h>

__device__ __forceinline__ float fast_tanh(float x) {
    float y;
    asm("tanh.approx.f32 %0, %1;" : "=f"(y) : "f"(x));
    return y;
}

__device__ __forceinline__ __half2 tanh2(__half2 v) {
    unsigned a = *reinterpret_cast<unsigned*>(&v), b;
    asm("tanh.approx.f16x2 %0, %1;" : "=r"(b) : "r"(a));
    return *reinterpret_cast<__half2*>(&b);
}

// Gate rows in 4H=20: i=[0,5), f=[5,10), g=[10,15), o=[15,20)
// sigmoid(z)=0.5*tanh(z/2)+0.5, the 1/2 folded into i/f/o weight rows.
// fp16 packing: pair A_j=(i_j,f_j), pair B_j=(g_j,o_j).
// Entire gate pre-activation (x-path + h-matmul) in HFMA2; c/tanh(c)/h in fp32.
__global__ __launch_bounds__(128) void lstm_kernel(
    const float* __restrict__ x,      // (32768, 600)
    const float* __restrict__ w_ih,   // (20, 1)
    const float* __restrict__ w_hh,   // (20, 5)
    const float* __restrict__ b_ih,   // (20,)
    const float* __restrict__ b_hh,   // (20,)
    const float* __restrict__ fc_w,   // (15, 5)
    const float* __restrict__ fc_b,   // (15,)
    const float* __restrict__ out_w,  // (1, 15)
    const float* __restrict__ out_b,  // (1,)
    float* __restrict__ out)          // (32768,)
{
    __shared__ __half2 s_wihA[5], s_wihB[5]; // (w_i*.5, w_f*.5), (w_g, w_o*.5)
    __shared__ __half2 s_bA[5],   s_bB[5];
    __shared__ __half2 s_whhA[25], s_whhB[25]; // [j*5+k]
    __shared__ float s_fcw[75];
    __shared__ float s_fcb[15];
    __shared__ float s_outw[15];
    __shared__ float s_outb;

    const int tid = threadIdx.x;
    if (tid < 5) {
        const int j = tid;
        s_wihA[j] = __floats2half2_rn(w_ih[j] * 0.5f,  w_ih[5 + j] * 0.5f);
        s_wihB[j] = __floats2half2_rn(w_ih[10 + j],    w_ih[15 + j] * 0.5f);
        s_bA[j] = __floats2half2_rn((b_ih[j] + b_hh[j]) * 0.5f,
                                    (b_ih[5 + j] + b_hh[5 + j]) * 0.5f);
        s_bB[j] = __floats2half2_rn((b_ih[10 + j] + b_hh[10 + j]),
                                    (b_ih[15 + j] + b_hh[15 + j]) * 0.5f);
    }
    if (tid < 25) {
        const int j = tid / 5, k = tid % 5;
        s_whhA[tid] = __floats2half2_rn(w_hh[j * 5 + k] * 0.5f,
                                        w_hh[(5 + j) * 5 + k] * 0.5f);
        s_whhB[tid] = __floats2half2_rn(w_hh[(10 + j) * 5 + k],
                                        w_hh[(15 + j) * 5 + k] * 0.5f);
    }
    if (tid < 75) s_fcw[tid] = fc_w[tid];
    if (tid < 15) { s_fcb[tid] = fc_b[tid]; s_outw[tid] = out_w[tid]; }
    if (tid == 0) s_outb = out_b[0];
    __syncthreads();

    // Hoist packed weights into registers (loop-invariant): 70 x 32-bit regs.
    __half2 wihA[5], wihB[5], bA[5], bB[5], whhA[25], whhB[25];
    #pragma unroll
    for (int j = 0; j < 5; j++) {
        wihA[j] = s_wihA[j]; wihB[j] = s_wihB[j];
        bA[j]   = s_bA[j];   bB[j]   = s_bB[j];
    }
    #pragma unroll
    for (int m = 0; m < 25; m++) { whhA[m] = s_whhA[m]; whhB[m] = s_whhB[m]; }

    const __half2 hA_s = __floats2half2_rn(0.5f, 0.5f);
    const __half2 hA_b = __floats2half2_rn(0.5f, 0.5f);
    const __half2 hB_s = __floats2half2_rn(1.0f, 0.5f);
    const __half2 hB_b = __floats2half2_rn(0.0f, 0.5f);

    const int seq = blockIdx.x * 128 + tid;
    const float* xr = x + (long)seq * 600;

    float h[5] = {0.f, 0.f, 0.f, 0.f, 0.f};
    float c[5] = {0.f, 0.f, 0.f, 0.f, 0.f};

    #pragma unroll 1
    for (int t0 = 0; t0 < 600; t0 += 4) {
        const float4 xv = *reinterpret_cast<const float4*>(xr + t0);
        float xs[4] = {xv.x, xv.y, xv.z, xv.w};
        #pragma unroll
        for (int u = 0; u < 4; u++) {
            const __half2 xx2 = __float2half2_rn(xs[u]);
            __half2 hh[5];
            #pragma unroll
            for (int k = 0; k < 5; k++) hh[k] = __float2half2_rn(h[k]);

            __half2 zA[5], zB[5];
            #pragma unroll
            for (int j = 0; j < 5; j++) {
                zA[j] = __hfma2(xx2, wihA[j], bA[j]);
                zB[j] = __hfma2(xx2, wihB[j], bB[j]);
                #pragma unroll
                for (int k = 0; k < 5; k++) {
                    zA[j] = __hfma2(hh[k], whhA[j * 5 + k], zA[j]);
                    zB[j] = __hfma2(hh[k], whhB[j * 5 + k], zB[j]);
                }
            }
            #pragma unroll
            for (int j = 0; j < 5; j++) {
                const __half2 actA = __hfma2(tanh2(zA[j]), hA_s, hA_b); // (i, f)
                const __half2 actB = __hfma2(tanh2(zB[j]), hB_s, hB_b); // (g, o)
                const __half2 m = __hmul2(actA, actB);                   // (i*g, f*o)
                const float ig = __low2float(m);
                const float fv = __high2float(actA);
                const float ov = __high2float(actB);
                c[j] = fmaf(fv, c[j], ig);
                h[j] = ov * fast_tanh(c[j]);
            }
        }
    }

    // Epilogue (fp32, exact): hid = h @ fc_w^T + fc_b ; out = sigmoid(hid @ out_w^T + out_b)
    float acc = s_outb;
    #pragma unroll
    for (int k = 0; k < 15; k++) {
        float hv = s_fcb[k];
        #pragma unroll
        for (int j = 0; j < 5; j++) hv = fmaf(h[j], s_fcw[k * 5 + j], hv);
        acc = fmaf(hv, s_outw[k], acc);
    }
    out[seq] = 1.0f / (1.0f + __expf(-acc));
}

extern "C" void kernel_launch(void* const* d_in, const int* in_sizes, int n_in,
                              void* d_out, int out_size) {
    const float* x    = (const float*)d_in[0];
    const float* w_ih = (const float*)d_in[1];
    const float* w_hh = (const float*)d_in[2];
    const float* b_ih = (const float*)d_in[3];
    const float* b_hh = (const float*)d_in[4];
    const float* fc_w = (const float*)d_in[5];
    const float* fc_b = (const float*)d_in[6];
    const float* out_w = (const float*)d_in[7];
    const float* out_b = (const float*)d_in[8];
    float* out = (float*)d_out;

    lstm_kernel<<<256, 128>>>(x, w_ih, w_hh, b_ih, b_hh, fc_w, fc_b,
                              out_w, out_b, out);
}

// round 6
// speedup vs baseline: 1.0545x; 1.0545x over previous
#include <cuda_runtime.h>
#include <cuda_fp16.h>

__device__ __forceinline__ __half2 tanh2(__half2 v) {
    unsigned a = *reinterpret_cast<unsigned*>(&v), b;
    asm("tanh.approx.f16x2 %0, %1;" : "=r"(b) : "r"(a));
    return *reinterpret_cast<__half2*>(&b);
}

__device__ __forceinline__ unsigned h2u(__half2 v) { return *reinterpret_cast<unsigned*>(&v); }
__device__ __forceinline__ __half2 u2h(unsigned v) { return *reinterpret_cast<__half2*>(&v); }

// Gate rows in 4H=20: i=[0,5), f=[5,10), g=[10,15), o=[15,20)
// sigmoid(z)=0.5*tanh(z/2)+0.5 with the 1/2 folded into i/f/o weight rows.
// fp16 pairs: A_j=(i_j,f_j), B_j=(g_j,o_j). c kept fp32; tanh(c) via paired
// tanh.approx.f16x2; h carried as packed half2 pairs; broadcasts via PRMT.
__global__ __launch_bounds__(128) void lstm_kernel(
    const float* __restrict__ x,      // (32768, 600)
    const float* __restrict__ w_ih,   // (20, 1)
    const float* __restrict__ w_hh,   // (20, 5)
    const float* __restrict__ b_ih,   // (20,)
    const float* __restrict__ b_hh,   // (20,)
    const float* __restrict__ fc_w,   // (15, 5)
    const float* __restrict__ fc_b,   // (15,)
    const float* __restrict__ out_w,  // (1, 15)
    const float* __restrict__ out_b,  // (1,)
    float* __restrict__ out)          // (32768,)
{
    __shared__ __half2 s_wihA[5], s_wihB[5];
    __shared__ __half2 s_bA[5],   s_bB[5];
    __shared__ __half2 s_whhA[25], s_whhB[25]; // [j*5+k]
    __shared__ float s_fcw[75];
    __shared__ float s_fcb[15];
    __shared__ float s_outw[15];
    __shared__ float s_outb;

    const int tid = threadIdx.x;
    if (tid < 5) {
        const int j = tid;
        s_wihA[j] = __floats2half2_rn(w_ih[j] * 0.5f,  w_ih[5 + j] * 0.5f);
        s_wihB[j] = __floats2half2_rn(w_ih[10 + j],    w_ih[15 + j] * 0.5f);
        s_bA[j] = __floats2half2_rn((b_ih[j] + b_hh[j]) * 0.5f,
                                    (b_ih[5 + j] + b_hh[5 + j]) * 0.5f);
        s_bB[j] = __floats2half2_rn((b_ih[10 + j] + b_hh[10 + j]),
                                    (b_ih[15 + j] + b_hh[15 + j]) * 0.5f);
    }
    if (tid < 25) {
        const int j = tid / 5, k = tid % 5;
        s_whhA[tid] = __floats2half2_rn(w_hh[j * 5 + k] * 0.5f,
                                        w_hh[(5 + j) * 5 + k] * 0.5f);
        s_whhB[tid] = __floats2half2_rn(w_hh[(10 + j) * 5 + k],
                                        w_hh[(15 + j) * 5 + k] * 0.5f);
    }
    if (tid < 75) s_fcw[tid] = fc_w[tid];
    if (tid < 15) { s_fcb[tid] = fc_b[tid]; s_outw[tid] = out_w[tid]; }
    if (tid == 0) s_outb = out_b[0];
    __syncthreads();

    __half2 wihA[5], wihB[5], bA[5], bB[5], whhA[25], whhB[25];
    #pragma unroll
    for (int j = 0; j < 5; j++) {
        wihA[j] = s_wihA[j]; wihB[j] = s_wihB[j];
        bA[j]   = s_bA[j];   bB[j]   = s_bB[j];
    }
    #pragma unroll
    for (int m = 0; m < 25; m++) { whhA[m] = s_whhA[m]; whhB[m] = s_whhB[m]; }

    const __half2 hA_s = __floats2half2_rn(0.5f, 0.5f);
    const __half2 hA_b = __floats2half2_rn(0.5f, 0.5f);
    const __half2 hB_s = __floats2half2_rn(1.0f, 0.5f);
    const __half2 hB_b = __floats2half2_rn(0.0f, 0.5f);

    const int seq = blockIdx.x * 128 + tid;
    const float* xr = x + (long)seq * 600;

    float c[5] = {0.f, 0.f, 0.f, 0.f, 0.f};
    __half2 hh[5];                       // broadcast pairs (h_k, h_k)
    #pragma unroll
    for (int k = 0; k < 5; k++) hh[k] = __float2half2_rn(0.f);

    #pragma unroll 1
    for (int t0 = 0; t0 < 600; t0 += 8) {
        const float4 xv0 = *reinterpret_cast<const float4*>(xr + t0);
        const float4 xv1 = *reinterpret_cast<const float4*>(xr + t0 + 4);
        float xs[8] = {xv0.x, xv0.y, xv0.z, xv0.w, xv1.x, xv1.y, xv1.z, xv1.w};

        // Hoisted x-path: independent of the recurrence -> stall filler.
        __half2 zxA[8][5], zxB[8][5];
        #pragma unroll
        for (int u = 0; u < 8; u++) {
            const __half2 xx2 = __float2half2_rn(xs[u]);
            #pragma unroll
            for (int j = 0; j < 5; j++) {
                zxA[u][j] = __hfma2(xx2, wihA[j], bA[j]);
                zxB[u][j] = __hfma2(xx2, wihB[j], bB[j]);
            }
        }

        #pragma unroll
        for (int u = 0; u < 8; u++) {
            __half2 zA[5], zB[5];
            #pragma unroll
            for (int j = 0; j < 5; j++) {
                zA[j] = zxA[u][j];
                zB[j] = zxB[u][j];
                #pragma unroll
                for (int k = 0; k < 5; k++) {
                    zA[j] = __hfma2(hh[k], whhA[j * 5 + k], zA[j]);
                    zB[j] = __hfma2(hh[k], whhB[j * 5 + k], zB[j]);
                }
            }
            __half2 actA[5], actB[5];
            #pragma unroll
            for (int j = 0; j < 5; j++) {
                actA[j] = __hfma2(tanh2(zA[j]), hA_s, hA_b); // (i, f)
                actB[j] = __hfma2(tanh2(zB[j]), hB_s, hB_b); // (g, o)
            }
            #pragma unroll
            for (int j = 0; j < 5; j++) {
                const __half2 m = __hmul2(actA[j], actB[j]); // (i*g, f*o)
                c[j] = fmaf(__high2float(actA[j]), c[j], __low2float(m));
            }
            // Paired tanh(c): 3 MUFU instead of 5.
            const __half2 tc01 = tanh2(__floats2half2_rn(c[0], c[1]));
            const __half2 tc23 = tanh2(__floats2half2_rn(c[2], c[3]));
            const __half2 tc44 = tanh2(__float2half2_rn(c[4]));
            // o pairs from actB high halves (PRMT on alu pipe)
            const __half2 o01 = u2h(__byte_perm(h2u(actB[0]), h2u(actB[1]), 0x7632));
            const __half2 o23 = u2h(__byte_perm(h2u(actB[2]), h2u(actB[3]), 0x7632));
            const __half2 o44 = u2h(__byte_perm(h2u(actB[4]), h2u(actB[4]), 0x3232));
            const __half2 h01 = __hmul2(o01, tc01);
            const __half2 h23 = __hmul2(o23, tc23);
            const __half2 h44 = __hmul2(o44, tc44);       // already (h4, h4)
            hh[0] = u2h(__byte_perm(h2u(h01), h2u(h01), 0x1010));
            hh[1] = u2h(__byte_perm(h2u(h01), h2u(h01), 0x3232));
            hh[2] = u2h(__byte_perm(h2u(h23), h2u(h23), 0x1010));
            hh[3] = u2h(__byte_perm(h2u(h23), h2u(h23), 0x3232));
            hh[4] = h44;
        }
    }

    // Epilogue (fp32): hid = h @ fc_w^T + fc_b ; out = sigmoid(hid @ out_w^T + out_b)
    float h[5];
    #pragma unroll
    for (int k = 0; k < 5; k++) h[k] = __low2float(hh[k]);
    float acc = s_outb;
    #pragma unroll
    for (int k = 0; k < 15; k++) {
        float hv = s_fcb[k];
        #pragma unroll
        for (int j = 0; j < 5; j++) hv = fmaf(h[j], s_fcw[k * 5 + j], hv);
        acc = fmaf(hv, s_outw[k], acc);
    }
    out[seq] = 1.0f / (1.0f + __expf(-acc));
}

extern "C" void kernel_launch(void* const* d_in, const int* in_sizes, int n_in,
                              void* d_out, int out_size) {
    const float* x    = (const float*)d_in[0];
    const float* w_ih = (const float*)d_in[1];
    const float* w_hh = (const float*)d_in[2];
    const float* b_ih = (const float*)d_in[3];
    const float* b_hh = (const float*)d_in[4];
    const float* fc_w = (const float*)d_in[5];
    const float* fc_b = (const float*)d_in[6];
    const float* out_w = (const float*)d_in[7];
    const float* out_b = (const float*)d_in[8];
    float* out = (float*)d_out;

    lstm_kernel<<<256, 128>>>(x, w_ih, w_hh, b_ih, b_hh, fc_w, fc_b,
                              out_w, out_b, out);
}